// round 9
// baseline (speedup 1.0000x reference)
#include <cuda_runtime.h>
#include <math_constants.h>

// x: [4,16,8192] f32 ; weights1: [16,16,64] f32 ; out: [4,16,4097] f32
#define NN    8192
#define N2    4097
#define NGEMM 128     // n-chunk blocks
#define NPTOT 256     // partials (2 halves per block)
#define NBLK  148
#define NTHR  512

// -------- device scratch --------
__device__ float g_P[NPTOT * 4096];       // partials (4 MB) [p][r*64+k]
__device__ float g_hq[64 * 256];          // hq transposed: [m][u], u=i*16+o
__device__ float g_u[64 * 64];            // u[r][m]
__device__ float g_v[64 * 64];            // v[r][m]
__device__ float g_zT[64 * 64];           // z transposed: [m'][r]

// -------- scoped sync state (self-resetting, epoch-based) --------
__device__ unsigned g_cnt_gemm[4] = {0, 0, 0, 0};
__device__ unsigned g_cnt_gemm2  = 0;
__device__ unsigned g_gen_gemm   = 0;
__device__ unsigned g_cnt_hq     = 0;
__device__ unsigned g_gen_hq     = 0;
__device__ unsigned g_cnt_z[4]   = {0, 0, 0, 0};
__device__ unsigned g_gen_z[4]   = {0, 0, 0, 0};
__device__ unsigned g_cnt_c      = 0;
__device__ unsigned g_gen_c      = 0;

__device__ __forceinline__ void arrive(unsigned* cnt, unsigned target, unsigned* gen)
{
    __threadfence();
    if (atomicAdd(cnt, 1u) == target - 1u) {
        *cnt = 0;
        __threadfence();
        atomicAdd(gen, 1u);
    }
}
__device__ __forceinline__ void wait_gen(unsigned* gen, unsigned cap)
{
    while (*(volatile unsigned*)gen == cap) __nanosleep(32);
    __threadfence();
}

// -------- packed f32x2 helpers --------
__device__ __forceinline__ unsigned long long pkdup(float a)
{
    unsigned long long r;
    asm("mov.b64 %0, {%1,%2};" : "=l"(r) : "f"(a), "f"(a));
    return r;
}
__device__ __forceinline__ void fma2(unsigned long long& d,
                                     unsigned long long a, unsigned long long b)
{
    asm("fma.rn.f32x2 %0, %1, %2, %0;" : "+l"(d) : "l"(a), "l"(b));
}
__device__ __forceinline__ float2 upk(unsigned long long v)
{
    float2 r;
    asm("mov.b64 {%0,%1}, %2;" : "=f"(r.x), "=f"(r.y) : "l"(v));
    return r;
}

// -------- shared memory --------
struct SmemA {
    float Xs[64][68];   // [nl][r] transposed
    float Cs[64][68];   // [nl][k] / [j][m]
    float ws[16][64];
    float v64[64];
};
struct SmemR {
    float red[8][64];
    float Ys[64];
    float hps[64];
    float v64[64];
};
struct SmemZ {
    float u16[16][68];
    float v16[16][68];
    float hzs[16][68];
    float v64[64];
};
struct SmemC {
    float zs[64][68];   // [m'][r]
    float Cs[64][36];   // [m'][kt]
};
union SmemU { SmemA a; SmemR r; SmemZ z; SmemC c; };

// phase-C cas table: column recurrence, 64 threads, 256 MUFU total
__device__ __forceinline__ void gen_ctab(float (*Cs)[36], int kbase, int tid)
{
    if (tid < 64) {
        const float W2 = 2.0f * CUDART_PI_F / 4097.0f;
        int kt = tid & 31, h = tid >> 5;
        int k = kbase + kt;
        int t0 = (k * (h * 32)) % 4097;
        int d  = k % 4097;
        float s, c, sd, cd;
        __sincosf((float)t0 * W2, &s, &c);
        __sincosf((float)d  * W2, &sd, &cd);
        #pragma unroll
        for (int j = 0; j < 32; j++) {
            Cs[h * 32 + j][kt] = c + s;
            float cn = fmaf(c, cd, -s * sd);
            float sn = fmaf(s, cd,  c * sd);
            c = cn; s = sn;
        }
    }
}

__global__ __launch_bounds__(NTHR, 1)
void k_fused(const float* __restrict__ x, const float* __restrict__ w,
             float* __restrict__ out)
{
    __shared__ SmemU sm;
    const int blk = blockIdx.x;
    const int tid = threadIdx.x;
    const int kbase = blk * 32;

    // capture epochs BEFORE any release can fire (releases are >=2us away)
    unsigned capG = 0, capH = 0, capZ = 0, capC = 0;
    if (tid == 0) {
        capG = *(volatile unsigned*)&g_gen_gemm;
        capH = *(volatile unsigned*)&g_gen_hq;
        if (blk < 4) capZ = *(volatile unsigned*)&g_gen_z[blk];
        capC = *(volatile unsigned*)&g_gen_c;
    }

    // ================= PHASE A: GEMM partials / hq =================
    if (blk < NGEMM) {
        const int n0 = blk * 64;
        const int row = tid >> 3;
        const int c8  = (tid & 7) * 8;
        float4 xa = *reinterpret_cast<const float4*>(x + row * NN + n0 + c8);
        float4 xb = *reinterpret_cast<const float4*>(x + row * NN + n0 + c8 + 4);

        if (tid < 128) {   // cas table: column recurrence, 2 sincos/thread
            const float W0 = 2.0f * CUDART_PI_F / 8192.0f;
            int k = tid & 63, h = tid >> 6;
            unsigned t0 = ((unsigned)(n0 + 32 * h) * (unsigned)k) & 8191u;
            float s, c, sd, cd;
            __sincosf((float)t0 * W0, &s, &c);
            __sincosf((float)k  * W0, &sd, &cd);
            #pragma unroll
            for (int j = 0; j < 32; j++) {
                sm.a.Cs[h * 32 + j][k] = c + s;
                float cn = fmaf(c, cd, -s * sd);
                float sn = fmaf(s, cd,  c * sd);
                c = cn; s = sn;
            }
        }
        {
            float xv[8] = {xa.x, xa.y, xa.z, xa.w, xb.x, xb.y, xb.z, xb.w};
            #pragma unroll
            for (int j = 0; j < 8; j++)
                sm.a.Xs[c8 + j][row] = xv[j];
        }
        __syncthreads();

        const int half = tid >> 8;
        const int tid2 = tid & 255;
        const int kq = tid2 & 15, rq = tid2 >> 4;
        const int r0 = rq * 4, k0 = kq * 4;
        const int nb = half * 32;
        unsigned long long a00 = 0, a01 = 0, a10 = 0, a11 = 0,
                           a20 = 0, a21 = 0, a30 = 0, a31 = 0;
        float4 xv = *reinterpret_cast<const float4*>(&sm.a.Xs[nb][r0]);
        ulonglong2 cv = *reinterpret_cast<const ulonglong2*>(&sm.a.Cs[nb][k0]);
        #pragma unroll
        for (int j = 0; j < 32; j++) {
            float4 xn; ulonglong2 cn;
            if (j < 31) {
                xn = *reinterpret_cast<const float4*>(&sm.a.Xs[nb + j + 1][r0]);
                cn = *reinterpret_cast<const ulonglong2*>(&sm.a.Cs[nb + j + 1][k0]);
            }
            unsigned long long d0 = pkdup(xv.x), d1 = pkdup(xv.y),
                               d2 = pkdup(xv.z), d3 = pkdup(xv.w);
            fma2(a00, d0, cv.x); fma2(a01, d0, cv.y);
            fma2(a10, d1, cv.x); fma2(a11, d1, cv.y);
            fma2(a20, d2, cv.x); fma2(a21, d2, cv.y);
            fma2(a30, d3, cv.x); fma2(a31, d3, cv.y);
            xv = xn; cv = cn;
        }
        float* P = g_P + (blk * 2 + half) * 4096;
        {
            float2 p0, p1;
            p0 = upk(a00); p1 = upk(a01);
            *reinterpret_cast<float4*>(P + (r0 + 0) * 64 + k0) =
                make_float4(p0.x, p0.y, p1.x, p1.y);
            p0 = upk(a10); p1 = upk(a11);
            *reinterpret_cast<float4*>(P + (r0 + 1) * 64 + k0) =
                make_float4(p0.x, p0.y, p1.x, p1.y);
            p0 = upk(a20); p1 = upk(a21);
            *reinterpret_cast<float4*>(P + (r0 + 2) * 64 + k0) =
                make_float4(p0.x, p0.y, p1.x, p1.y);
            p0 = upk(a30); p1 = upk(a31);
            *reinterpret_cast<float4*>(P + (r0 + 3) * 64 + k0) =
                make_float4(p0.x, p0.y, p1.x, p1.y);
        }
        __syncthreads();
        if (tid == 0) {          // two-level arrival: 32 per sub-counter
            __threadfence();
            if (atomicAdd(&g_cnt_gemm[blk & 3], 1u) == 31u) {
                if (atomicAdd(&g_cnt_gemm2, 1u) == 3u) {
                    g_cnt_gemm[0] = 0; g_cnt_gemm[1] = 0;
                    g_cnt_gemm[2] = 0; g_cnt_gemm[3] = 0;
                    g_cnt_gemm2 = 0;
                    __threadfence();
                    atomicAdd(&g_gen_gemm, 1u);
                }
            }
        }
    } else if (blk < NGEMM + 16) {
        // hq: rows u0..u0+15, hq[u][m] = sum_j w[u][j]*cas64[j][m] (transposed)
        const int u0 = (blk - NGEMM) * 16;
        #pragma unroll
        for (int q = 0; q < 2; q++) {
            int idx = tid + q * NTHR;
            sm.a.ws[idx >> 6][idx & 63] = w[u0 * 64 + idx];
        }
        if (tid < 64) {
            const float W1 = 2.0f * CUDART_PI_F / 64.0f;
            float s, c;
            __sincosf((float)tid * W1, &s, &c);
            sm.a.v64[tid] = c + s;
        }
        __syncthreads();
        #pragma unroll
        for (int q = 0; q < 8; q++) {
            int idx = tid + q * NTHR;
            int j = idx >> 6, m = idx & 63;
            sm.a.Cs[j][m] = sm.a.v64[(j * m) & 63];
        }
        __syncthreads();
        #pragma unroll
        for (int q = 0; q < 2; q++) {
            int idx = tid + q * NTHR;
            int ul = idx >> 6, m = idx & 63;
            float acc = 0.f;
            #pragma unroll
            for (int j = 0; j < 64; j++)
                acc = fmaf(sm.a.ws[ul][j], sm.a.Cs[j][m], acc);
            g_hq[m * 256 + u0 + ul] = acc;
        }
        __syncthreads();
        if (tid == 0) arrive(&g_cnt_hq, 16u, &g_gen_hq);
    } else {
        return;   // blocks 144-147: no duties
    }

    // ================= PHASE R: per-row reduce + hp + (u,v) (blocks 0-63) ===
    if (blk < 64) {
        if (tid == 0) wait_gen(&g_gen_gemm, capG);
        __syncthreads();

        const int r = blk;
        if (tid < 64) {
            const float W1 = 2.0f * CUDART_PI_F / 64.0f;
            float s, c;
            __sincosf((float)tid * W1, &s, &c);
            sm.r.v64[tid] = c + s;
        }
        {
            const int pg = tid >> 6;          // 0..7, each sums 32 partials
            const int k  = tid & 63;
            const float* P = g_P + r * 64 + k + pg * 32 * 4096;
            float a[8] = {};
            #pragma unroll
            for (int p = 0; p < 32; p += 8) {
                #pragma unroll
                for (int i = 0; i < 8; i++)
                    a[i] += P[(p + i) * 4096];
            }
            sm.r.red[pg][k] = ((a[0] + a[1]) + (a[2] + a[3]))
                            + ((a[4] + a[5]) + (a[6] + a[7]));
        }
        __syncthreads();
        if (tid < 64) {
            float s = 0.f;
            #pragma unroll
            for (int g = 0; g < 8; g++) s += sm.r.red[g][tid];
            sm.r.Ys[tid] = s;
        }
        __syncthreads();
        if (tid < 64) {
            const int m = tid;
            float acc = 0.f;
            #pragma unroll
            for (int k = 0; k < 64; k++)
                acc = fmaf(sm.r.Ys[k], sm.r.v64[(k * m) & 63], acc);
            sm.r.hps[m] = acc;
        }
        __syncthreads();
        if (tid < 64) {
            const int m = tid, mr = (64 - m) & 63;
            float a = sm.r.hps[m], b2 = sm.r.hps[mr];
            g_u[r * 64 + m] = a + b2;
            g_v[r * 64 + m] = a - b2;
        }
        __syncthreads();
        if (tid == 0) arrive(&g_cnt_z[r >> 4], 16u, &g_gen_z[r >> 4]);
    }

    // ========== ctab pregen for blocks 4-128 (off critical path) ==========
    if (blk >= 4 && blk < 129)
        gen_ctab(sm.c.Cs, kbase, tid);

    // ================= PHASE Z: hz + z (blocks 0-3) =================
    if (blk < 4) {
        const int b = blk;
        if (tid == 0) {
            wait_gen(&g_gen_z[b], capZ);
            while (*(volatile unsigned*)&g_gen_hq == capH) __nanosleep(32);
            __threadfence();
        }
        __syncthreads();

        if (tid < 64) {
            const float W1 = 2.0f * CUDART_PI_F / 64.0f;
            float s, c;
            __sincosf((float)tid * W1, &s, &c);
            sm.z.v64[tid] = c + s;
        }
        #pragma unroll
        for (int q = 0; q < 2; q++) {
            int idx = tid + q * NTHR;
            int i = idx >> 6, m = idx & 63;
            sm.z.u16[i][m] = g_u[b * 1024 + idx];
            sm.z.v16[i][m] = g_v[b * 1024 + idx];
        }
        __syncthreads();
        #pragma unroll
        for (int q = 0; q < 2; q++) {
            int idx = tid + q * NTHR;
            int m = idx >> 4, o = idx & 15;
            int mr = (64 - m) & 63;
            const float* hq1 = g_hq + m  * 256 + o;
            const float* hq2 = g_hq + mr * 256 + o;
            float acc = 0.f;
            #pragma unroll
            for (int i = 0; i < 16; i++) {
                acc = fmaf(sm.z.u16[i][m], hq1[i * 16], acc);
                acc = fmaf(sm.z.v16[i][m], hq2[i * 16], acc);
            }
            sm.z.hzs[o][m] = 0.5f * acc;
        }
        __syncthreads();
        #pragma unroll
        for (int q = 0; q < 2; q++) {
            int idx = tid + q * NTHR;
            int o = idx >> 6, mp = idx & 63;
            float acc = 0.f;
            #pragma unroll
            for (int m = 0; m < 64; m++)
                acc = fmaf(sm.z.hzs[o][m], sm.z.v64[(m * mp) & 63], acc);
            g_zT[mp * 64 + b * 16 + o] = acc * (1.0f / 4096.0f);
        }
        __syncthreads();
        if (tid == 0) arrive(&g_cnt_c, 4u, &g_gen_c);
        gen_ctab(sm.c.Cs, kbase, tid);   // aliases sm.z: after __syncthreads
    }

    // ================= PHASE C: final DHT (blocks 0-128) =================
    if (blk < 129) {
        if (tid == 0) wait_gen(&g_gen_c, capC);
        __syncthreads();

        #pragma unroll
        for (int q = 0; q < 2; q++) {
            int i4 = tid + q * NTHR;
            float4 v = *reinterpret_cast<const float4*>(g_zT + i4 * 4);
            int f = i4 * 4;
            *reinterpret_cast<float4*>(&sm.c.zs[f >> 6][f & 63]) = v;
        }
        __syncthreads();

        const int ktq = tid & 31;
        const int rq  = tid >> 5;
        const int r0  = rq * 4;
        const int k   = kbase + ktq;

        unsigned long long a01 = 0, a23 = 0;
        ulonglong2 zp = *reinterpret_cast<const ulonglong2*>(&sm.c.zs[0][r0]);
        float cvv = sm.c.Cs[0][ktq];
        #pragma unroll
        for (int mm = 0; mm < 64; mm++) {
            ulonglong2 zn; float cn;
            if (mm < 63) {
                zn = *reinterpret_cast<const ulonglong2*>(&sm.c.zs[mm + 1][r0]);
                cn = sm.c.Cs[mm + 1][ktq];
            }
            unsigned long long cd = pkdup(cvv);
            fma2(a01, zp.x, cd);
            fma2(a23, zp.y, cd);
            zp = zn; cvv = cn;
        }
        const float SCL = 1.0f / 262208.0f;
        if (k < N2) {
            float2 p01 = upk(a01), p23 = upk(a23);
            out[(r0 + 0) * N2 + k] = p01.x * SCL;
            out[(r0 + 1) * N2 + k] = p01.y * SCL;
            out[(r0 + 2) * N2 + k] = p23.x * SCL;
            out[(r0 + 3) * N2 + k] = p23.y * SCL;
        }
    }
}

// ============================================================
extern "C" void kernel_launch(void* const* d_in, const int* in_sizes, int n_in,
                              void* d_out, int out_size)
{
    const float* x = (const float*)d_in[0];   // [4,16,8192]
    const float* w = (const float*)d_in[1];   // [16,16,64]
    float* out = (float*)d_out;               // [4,16,4097]

    k_fused<<<NBLK, NTHR>>>(x, w, out);
}

// round 11
// speedup vs baseline: 1.5046x; 1.5046x over previous
#include <cuda_runtime.h>
#include <math_constants.h>

// x: [4,16,8192] f32 ; weights1: [16,16,64] f32 ; out: [4,16,4097] f32
#define NN    8192
#define N2    4097
#define NGEMM 128     // n-chunk blocks
#define NPTOT 256     // partials (2 halves per block)
#define NBLK  148
#define NTHR  512

// -------- device scratch --------
__device__ float g_P[NPTOT * 4096];       // partials (4 MB) [p][r*64+k]
__device__ float g_hq[64 * 256];          // hq transposed: [m][u], u=i*16+o
__device__ float g_u[64 * 64];            // u[r][m]
__device__ float g_v[64 * 64];            // v[r][m]
__device__ float g_zT[64 * 64];           // z transposed: [m'][r]

// -------- grid barrier (1 CTA/SM, all resident) --------
__device__ volatile unsigned g_bar_gen = 0;
__device__ unsigned g_bar_count = 0;

__device__ __forceinline__ void grid_bar()
{
    __syncthreads();
    if (threadIdx.x == 0) {
        __threadfence();
        unsigned gen = g_bar_gen;
        if (atomicAdd(&g_bar_count, 1u) == (unsigned)(NBLK - 1)) {
            g_bar_count = 0;
            __threadfence();
            g_bar_gen = gen + 1u;
        } else {
            while (g_bar_gen == gen) __nanosleep(32);
        }
        __threadfence();
    }
    __syncthreads();
}

// -------- per-batch R->Z signal (only 4 spinner threads chip-wide) --------
__device__ unsigned g_cnt_z[4] = {0, 0, 0, 0};
__device__ volatile unsigned g_gen_z[4] = {0, 0, 0, 0};

// -------- packed f32x2 helpers --------
__device__ __forceinline__ unsigned long long pkdup(float a)
{
    unsigned long long r;
    asm("mov.b64 %0, {%1,%2};" : "=l"(r) : "f"(a), "f"(a));
    return r;
}
__device__ __forceinline__ void fma2(unsigned long long& d,
                                     unsigned long long a, unsigned long long b)
{
    asm("fma.rn.f32x2 %0, %1, %2, %0;" : "+l"(d) : "l"(a), "l"(b));
}
__device__ __forceinline__ float2 upk(unsigned long long v)
{
    float2 r;
    asm("mov.b64 {%0,%1}, %2;" : "=f"(r.x), "=f"(r.y) : "l"(v));
    return r;
}

// -------- shared memory --------
struct SmemA {
    float Xs[64][68];   // [nl][r] transposed
    float Cs[64][68];   // [nl][k] / [j][m]
    float ws[16][64];
    float v64[64];
};
struct SmemR {
    float red[8][64];
    float Ys[64];
    float hps[64];
    float v64[64];
};
struct SmemZ {
    float u16[16][68];
    float v16[16][68];
    float hzs[16][68];
    float v64[64];
};
struct SmemC {
    float zs[64][68];   // [m'][r]
    float Cs[64][36];   // [m'][kt]
};
union SmemU { SmemA a; SmemR r; SmemZ z; SmemC c; };

// phase-C cas table: column recurrence, 64 threads, 256 MUFU total
__device__ __forceinline__ void gen_ctab(float (*Cs)[36], int kbase, int tid)
{
    if (tid < 64) {
        const float W2 = 2.0f * CUDART_PI_F / 4097.0f;
        int kt = tid & 31, h = tid >> 5;
        int k = kbase + kt;
        int t0 = (k * (h * 32)) % 4097;
        int d  = k % 4097;
        float s, c, sd, cd;
        __sincosf((float)t0 * W2, &s, &c);
        __sincosf((float)d  * W2, &sd, &cd);
        #pragma unroll
        for (int j = 0; j < 32; j++) {
            Cs[h * 32 + j][kt] = c + s;
            float cn = fmaf(c, cd, -s * sd);
            float sn = fmaf(s, cd,  c * sd);
            c = cn; s = sn;
        }
    }
}

__global__ __launch_bounds__(NTHR, 1)
void k_fused(const float* __restrict__ x, const float* __restrict__ w,
             float* __restrict__ out)
{
    __shared__ SmemU sm;
    const int blk = blockIdx.x;
    const int tid = threadIdx.x;
    const int kbase = blk * 32;

    // capture Z epoch before any release can fire (release is >5us away)
    unsigned capZ = 0;
    if (blk < 4 && tid == 0) capZ = g_gen_z[blk];

    // ================= PHASE A: GEMM partials / hq =================
    if (blk < NGEMM) {
        const int n0 = blk * 64;
        const int row = tid >> 3;
        const int c8  = (tid & 7) * 8;
        float4 xa = *reinterpret_cast<const float4*>(x + row * NN + n0 + c8);
        float4 xb = *reinterpret_cast<const float4*>(x + row * NN + n0 + c8 + 4);

        if (tid < 128) {   // cas table: column recurrence, 2 sincos/thread
            const float W0 = 2.0f * CUDART_PI_F / 8192.0f;
            int k = tid & 63, h = tid >> 6;
            unsigned t0 = ((unsigned)(n0 + 32 * h) * (unsigned)k) & 8191u;
            float s, c, sd, cd;
            __sincosf((float)t0 * W0, &s, &c);
            __sincosf((float)k  * W0, &sd, &cd);
            #pragma unroll
            for (int j = 0; j < 32; j++) {
                sm.a.Cs[h * 32 + j][k] = c + s;
                float cn = fmaf(c, cd, -s * sd);
                float sn = fmaf(s, cd,  c * sd);
                c = cn; s = sn;
            }
        }
        {
            float xv[8] = {xa.x, xa.y, xa.z, xa.w, xb.x, xb.y, xb.z, xb.w};
            #pragma unroll
            for (int j = 0; j < 8; j++)
                sm.a.Xs[c8 + j][row] = xv[j];
        }
        __syncthreads();

        const int half = tid >> 8;
        const int tid2 = tid & 255;
        const int kq = tid2 & 15, rq = tid2 >> 4;
        const int r0 = rq * 4, k0 = kq * 4;
        const int nb = half * 32;
        unsigned long long a00 = 0, a01 = 0, a10 = 0, a11 = 0,
                           a20 = 0, a21 = 0, a30 = 0, a31 = 0;
        float4 xv = *reinterpret_cast<const float4*>(&sm.a.Xs[nb][r0]);
        ulonglong2 cv = *reinterpret_cast<const ulonglong2*>(&sm.a.Cs[nb][k0]);
        #pragma unroll
        for (int j = 0; j < 32; j++) {
            float4 xn; ulonglong2 cn;
            if (j < 31) {
                xn = *reinterpret_cast<const float4*>(&sm.a.Xs[nb + j + 1][r0]);
                cn = *reinterpret_cast<const ulonglong2*>(&sm.a.Cs[nb + j + 1][k0]);
            }
            unsigned long long d0 = pkdup(xv.x), d1 = pkdup(xv.y),
                               d2 = pkdup(xv.z), d3 = pkdup(xv.w);
            fma2(a00, d0, cv.x); fma2(a01, d0, cv.y);
            fma2(a10, d1, cv.x); fma2(a11, d1, cv.y);
            fma2(a20, d2, cv.x); fma2(a21, d2, cv.y);
            fma2(a30, d3, cv.x); fma2(a31, d3, cv.y);
            xv = xn; cv = cn;
        }
        float* P = g_P + (blk * 2 + half) * 4096;
        {
            float2 p0, p1;
            p0 = upk(a00); p1 = upk(a01);
            *reinterpret_cast<float4*>(P + (r0 + 0) * 64 + k0) =
                make_float4(p0.x, p0.y, p1.x, p1.y);
            p0 = upk(a10); p1 = upk(a11);
            *reinterpret_cast<float4*>(P + (r0 + 1) * 64 + k0) =
                make_float4(p0.x, p0.y, p1.x, p1.y);
            p0 = upk(a20); p1 = upk(a21);
            *reinterpret_cast<float4*>(P + (r0 + 2) * 64 + k0) =
                make_float4(p0.x, p0.y, p1.x, p1.y);
            p0 = upk(a30); p1 = upk(a31);
            *reinterpret_cast<float4*>(P + (r0 + 3) * 64 + k0) =
                make_float4(p0.x, p0.y, p1.x, p1.y);
        }
    } else if (blk < NGEMM + 16) {
        // hq: rows u0..u0+15, hq[u][m] = sum_j w[u][j]*cas64[j][m] (transposed)
        const int u0 = (blk - NGEMM) * 16;
        #pragma unroll
        for (int q = 0; q < 2; q++) {
            int idx = tid + q * NTHR;
            sm.a.ws[idx >> 6][idx & 63] = w[u0 * 64 + idx];
        }
        if (tid < 64) {
            const float W1 = 2.0f * CUDART_PI_F / 64.0f;
            float s, c;
            __sincosf((float)tid * W1, &s, &c);
            sm.a.v64[tid] = c + s;
        }
        __syncthreads();
        #pragma unroll
        for (int q = 0; q < 8; q++) {
            int idx = tid + q * NTHR;
            int j = idx >> 6, m = idx & 63;
            sm.a.Cs[j][m] = sm.a.v64[(j * m) & 63];
        }
        __syncthreads();
        #pragma unroll
        for (int q = 0; q < 2; q++) {
            int idx = tid + q * NTHR;
            int ul = idx >> 6, m = idx & 63;
            float acc = 0.f;
            #pragma unroll
            for (int j = 0; j < 64; j++)
                acc = fmaf(sm.a.ws[ul][j], sm.a.Cs[j][m], acc);
            g_hq[m * 256 + u0 + ul] = acc;
        }
    }

    grid_bar();   // A -> R (also covers hq -> Z)

    // ========== PHASE R (blocks 0-63) / C-table pregen (64-128) ==========
    if (blk < 64) {
        const int r = blk;
        if (tid < 64) {
            const float W1 = 2.0f * CUDART_PI_F / 64.0f;
            float s, c;
            __sincosf((float)tid * W1, &s, &c);
            sm.r.v64[tid] = c + s;
        }
        {
            const int pg = tid >> 6;          // 0..7, each sums 32 partials
            const int k  = tid & 63;
            const float* P = g_P + r * 64 + k + pg * 32 * 4096;
            float a[8] = {};
            #pragma unroll
            for (int p = 0; p < 32; p += 8) {
                #pragma unroll
                for (int i = 0; i < 8; i++)
                    a[i] += P[(p + i) * 4096];
            }
            sm.r.red[pg][k] = ((a[0] + a[1]) + (a[2] + a[3]))
                            + ((a[4] + a[5]) + (a[6] + a[7]));
        }
        __syncthreads();
        if (tid < 64) {
            float s = 0.f;
            #pragma unroll
            for (int g = 0; g < 8; g++) s += sm.r.red[g][tid];
            sm.r.Ys[tid] = s;
        }
        __syncthreads();
        if (tid < 64) {
            const int m = tid;
            float acc = 0.f;
            #pragma unroll
            for (int k = 0; k < 64; k++)
                acc = fmaf(sm.r.Ys[k], sm.r.v64[(k * m) & 63], acc);
            sm.r.hps[m] = acc;
        }
        __syncthreads();
        if (tid < 64) {
            const int m = tid, mr = (64 - m) & 63;
            float a = sm.r.hps[m], b2 = sm.r.hps[mr];
            g_u[r * 64 + m] = a + b2;
            g_v[r * 64 + m] = a - b2;
        }
        __syncthreads();
        if (tid == 0) {       // signal this row's batch
            __threadfence();
            const int b = r >> 4;
            if (atomicAdd(&g_cnt_z[b], 1u) == 15u) {
                g_cnt_z[b] = 0;
                __threadfence();
                g_gen_z[b] = g_gen_z[b] + 1u;
            }
        }
        // blocks 4-63 build their Phase-C table now (no overlap with sm.r:
        // sm.c.Cs sits at byte 17408, far past SmemR's ~2.8KB footprint)
        if (blk >= 4)
            gen_ctab(sm.c.Cs, kbase, tid);
    } else if (blk < 129) {
        gen_ctab(sm.c.Cs, kbase, tid);   // idle blocks pregen C table
    }

    // ================= PHASE Z: hz + z (blocks 0-3 only spin) ==============
    if (blk < 4) {
        const int b = blk;
        if (tid == 0) {     // only 4 spinner threads chip-wide
            while (g_gen_z[b] == capZ) __nanosleep(32);
            __threadfence();
        }
        __syncthreads();

        if (tid < 64) {
            const float W1 = 2.0f * CUDART_PI_F / 64.0f;
            float s, c;
            __sincosf((float)tid * W1, &s, &c);
            sm.z.v64[tid] = c + s;
        }
        #pragma unroll
        for (int q = 0; q < 2; q++) {
            int idx = tid + q * NTHR;
            int i = idx >> 6, m = idx & 63;
            sm.z.u16[i][m] = g_u[b * 1024 + idx];
            sm.z.v16[i][m] = g_v[b * 1024 + idx];
        }
        __syncthreads();
        #pragma unroll
        for (int q = 0; q < 2; q++) {
            int idx = tid + q * NTHR;
            int m = idx >> 4, o = idx & 15;
            int mr = (64 - m) & 63;
            const float* hq1 = g_hq + m  * 256 + o;
            const float* hq2 = g_hq + mr * 256 + o;
            float acc = 0.f;
            #pragma unroll
            for (int i = 0; i < 16; i++) {
                acc = fmaf(sm.z.u16[i][m], hq1[i * 16], acc);
                acc = fmaf(sm.z.v16[i][m], hq2[i * 16], acc);
            }
            sm.z.hzs[o][m] = 0.5f * acc;
        }
        __syncthreads();
        #pragma unroll
        for (int q = 0; q < 2; q++) {
            int idx = tid + q * NTHR;
            int o = idx >> 6, mp = idx & 63;
            float acc = 0.f;
            #pragma unroll
            for (int m = 0; m < 64; m++)
                acc = fmaf(sm.z.hzs[o][m], sm.z.v64[(m * mp) & 63], acc);
            g_zT[mp * 64 + b * 16 + o] = acc * (1.0f / 4096.0f);
        }
    }

    grid_bar();   // Z -> C

    // ================= PHASE C: final DHT (blocks 0-128) =================
    if (blk < 129) {
        if (blk < 4)
            gen_ctab(sm.c.Cs, kbase, tid);   // Z-workers build table now
        // load zT (hot in L2)
        #pragma unroll
        for (int q = 0; q < 2; q++) {
            int i4 = tid + q * NTHR;
            float4 v = *reinterpret_cast<const float4*>(g_zT + i4 * 4);
            int f = i4 * 4;
            *reinterpret_cast<float4*>(&sm.c.zs[f >> 6][f & 63]) = v;
        }
        __syncthreads();

        const int ktq = tid & 31;
        const int rq  = tid >> 5;
        const int r0  = rq * 4;
        const int k   = kbase + ktq;

        unsigned long long a01 = 0, a23 = 0;
        ulonglong2 zp = *reinterpret_cast<const ulonglong2*>(&sm.c.zs[0][r0]);
        float cvv = sm.c.Cs[0][ktq];
        #pragma unroll
        for (int mm = 0; mm < 64; mm++) {
            ulonglong2 zn; float cn;
            if (mm < 63) {
                zn = *reinterpret_cast<const ulonglong2*>(&sm.c.zs[mm + 1][r0]);
                cn = sm.c.Cs[mm + 1][ktq];
            }
            unsigned long long cd = pkdup(cvv);
            fma2(a01, zp.x, cd);
            fma2(a23, zp.y, cd);
            zp = zn; cvv = cn;
        }
        const float SCL = 1.0f / 262208.0f;
        if (k < N2) {
            float2 p01 = upk(a01), p23 = upk(a23);
            out[(r0 + 0) * N2 + k] = p01.x * SCL;
            out[(r0 + 1) * N2 + k] = p01.y * SCL;
            out[(r0 + 2) * N2 + k] = p23.x * SCL;
            out[(r0 + 3) * N2 + k] = p23.y * SCL;
        }
    }
}

// ============================================================
extern "C" void kernel_launch(void* const* d_in, const int* in_sizes, int n_in,
                              void* d_out, int out_size)
{
    const float* x = (const float*)d_in[0];   // [4,16,8192]
    const float* w = (const float*)d_in[1];   // [16,16,64]
    float* out = (float*)d_out;               // [4,16,4097]

    k_fused<<<NBLK, NTHR>>>(x, w, out);
}